// round 11
// baseline (speedup 1.0000x reference)
#include <cuda_runtime.h>
#include <cstdint>
#include <cstddef>

#define BATCH   8
#define NPTS    8192
#define CDIM    6
#define NG      512
#define GS      32
#define NSLAB   256
#define FULLMASK 0xffffffffu
#define PINF    __int_as_float(0x7f800000)

// output layout: neighborhood, center, idx (flattened tuple order, all f32)
#define NB_SZ  (BATCH * NG * GS * CDIM)   // 786432
#define C_OFF  (NB_SZ)
#define C_SZ   (BATCH * NG * 3)           // 12288
#define I_OFF  (C_OFF + C_SZ)             // 798720
#define I_SZ   (BATCH * NG * GS)          // 131072

// scratch (no allocations allowed -> __device__ globals)
__device__ float4 g_pts[BATCH * NPTS];    // original order: (x, y, z, |p|^2)
__device__ float4 g_spts[BATCH * NPTS];   // x-sorted order
__device__ int    g_sidx[BATCH * NPTS];   // sorted pos -> original index
__device__ float2 g_slab[BATCH * NSLAB];  // per-32-point slab (xmin, xmax)
__device__ float4 g_center[BATCH * NG];   // (cx, cy, cz, |c|^2)
__device__ int    g_prog[BATCH];          // highest published center index
__device__ int    g_pts_ready[BATCH];
__device__ int    g_sort_done[BATCH];

// ---------------------------------------------------------------------------
// packed f32x2 helpers (FFMA2; per-component RN rounding identical to scalar)
// ---------------------------------------------------------------------------
__device__ __forceinline__ unsigned long long pk2(float lo, float hi) {
    unsigned long long r;
    asm("mov.b64 %0, {%1, %2};" : "=l"(r)
        : "r"(__float_as_uint(lo)), "r"(__float_as_uint(hi)));
    return r;
}
__device__ __forceinline__ void upk2(unsigned long long v, float& lo, float& hi) {
    unsigned a, b;
    asm("mov.b64 {%0, %1}, %2;" : "=r"(a), "=r"(b) : "l"(v));
    lo = __uint_as_float(a); hi = __uint_as_float(b);
}
__device__ __forceinline__ unsigned long long add2(unsigned long long a, unsigned long long b) {
    unsigned long long r;
    asm("add.rn.f32x2 %0, %1, %2;" : "=l"(r) : "l"(a), "l"(b));
    return r;
}
__device__ __forceinline__ unsigned long long mul2(unsigned long long a, unsigned long long b) {
    unsigned long long r;
    asm("mul.rn.f32x2 %0, %1, %2;" : "=l"(r) : "l"(a), "l"(b));
    return r;
}
__device__ __forceinline__ unsigned long long fma2(unsigned long long a, unsigned long long b,
                                                   unsigned long long c) {
    unsigned long long r;
    asm("fma.rn.f32x2 %0, %1, %2, %3;" : "=l"(r) : "l"(a), "l"(b), "l"(c));
    return r;
}

__device__ __forceinline__ float sumsq3(float x, float y, float z) {
    float t = __fmul_rn(x, x);
    t = __fmaf_rn(y, y, t);
    t = __fmaf_rn(z, z, t);
    return t;
}

// release/acquire publish of the center progress counter (tid-0 owns all
// center writes, so a release store orders them; no MEMBAR needed)
__device__ __forceinline__ void rel_store(int* p, int v) {
    asm volatile("st.release.gpu.s32 [%0], %1;" :: "l"(p), "r"(v) : "memory");
}
__device__ __forceinline__ int acq_load(const int* p) {
    int v;
    asm volatile("ld.acquire.gpu.s32 %0, [%1];" : "=r"(v) : "l"(p) : "memory");
    return v;
}

#define FT 512
#define FPS_SMEM ((size_t)(3 * NPTS) * sizeof(float) + 64 * sizeof(unsigned))

// static shared (roles use disjoint subsets)
__shared__ float  s_red[64];
__shared__ int    s_hist[NSLAB];
__shared__ float  s_mm[2];
__shared__ float2 k_slab[NSLAB];
__shared__ float  k_bufD[16][64];
__shared__ int    k_bufI[16][64];
__shared__ float  k_mD[8][32];
__shared__ int    k_mI[8][32];

// ---------------------------------------------------------------------------
// FPS role: monolithic 512-step loop (reverted to the proven R9 structure).
// Changes vs R9: (1) tree-structured local argmax (same lowest-index-on-tie
// semantics, shorter dependency chain); (2) release-store publish instead of
// threadfence+atomicExch. Distance arithmetic byte-identical.
// ---------------------------------------------------------------------------
__device__ void fps_role(const float* __restrict__ xyz, float* __restrict__ out,
                         int out_size, int b, char* dsm) {
    const int tid = threadIdx.x;
    float* sx = (float*)dsm;
    float* sy = sx + NPTS;
    float* sz = sx + 2 * NPTS;
    unsigned* sv   = (unsigned*)(sx + 3 * NPTS);
    unsigned* sidx = sv + 32;

    const float* base = xyz + (size_t)b * NPTS * CDIM;
    unsigned long long pxx[8], pyy[8], pzz[8];
    float dist[16];
    float prx = 0.f, pry = 0.f, prz = 0.f;
#pragma unroll
    for (int j = 0; j < 16; j++) {
        int i = j * FT + tid;
        float x = base[i * CDIM + 0];
        float y = base[i * CDIM + 1];
        float z = base[i * CDIM + 2];
        sx[i] = x; sy[i] = y; sz[i] = z;
        g_pts[b * NPTS + i] = make_float4(x, y, z, sumsq3(x, y, z));
        dist[j] = PINF;
        if ((j & 1) == 0) { prx = x; pry = y; prz = z; }
        else {
            pxx[j >> 1] = pk2(prx, x);
            pyy[j >> 1] = pk2(pry, y);
            pzz[j >> 1] = pk2(prz, z);
        }
    }
    __threadfence();                       // g_pts written by ALL threads
    __syncthreads();
    if (tid == 0) atomicExch(&g_pts_ready[b], 1);

    float qx = sx[0], qy = sy[0], qz = sz[0];
    if (tid == 0) {
        g_center[b * NG] = make_float4(qx, qy, qz, sumsq3(qx, qy, qz));
        if (out_size >= C_OFF + C_SZ) {
            out[C_OFF + (size_t)(b * NG) * 3 + 0] = qx;
            out[C_OFF + (size_t)(b * NG) * 3 + 1] = qy;
            out[C_OFF + (size_t)(b * NG) * 3 + 2] = qz;
        }
    }

    const int lane = tid & 31, wid = tid >> 5;
    for (int k = 1; k < NG; k++) {
        const unsigned long long nqx2 = pk2(-qx, -qx);
        const unsigned long long nqy2 = pk2(-qy, -qy);
        const unsigned long long nqz2 = pk2(-qz, -qz);
#pragma unroll
        for (int j = 0; j < 8; j++) {
            unsigned long long dx2 = add2(pxx[j], nqx2);
            unsigned long long dy2 = add2(pyy[j], nqy2);
            unsigned long long dz2 = add2(pzz[j], nqz2);
            unsigned long long t  = mul2(dx2, dx2);
            t = fma2(dy2, dy2, t);
            t = fma2(dz2, dz2, t);
            float dlo, dhi; upk2(t, dlo, dhi);
            dist[2 * j]     = fminf(dist[2 * j], dlo);
            dist[2 * j + 1] = fminf(dist[2 * j + 1], dhi);
        }
        // tree max of the 16 local dists (depth 4), then lowest index among
        // equals (depth-4 min tree) — identical semantics to the serial scan.
        float m0 = fmaxf(dist[0], dist[1]),   m1 = fmaxf(dist[2], dist[3]);
        float m2 = fmaxf(dist[4], dist[5]),   m3 = fmaxf(dist[6], dist[7]);
        float m4 = fmaxf(dist[8], dist[9]),   m5 = fmaxf(dist[10], dist[11]);
        float m6 = fmaxf(dist[12], dist[13]), m7 = fmaxf(dist[14], dist[15]);
        m0 = fmaxf(m0, m1); m2 = fmaxf(m2, m3); m4 = fmaxf(m4, m5); m6 = fmaxf(m6, m7);
        m0 = fmaxf(m0, m2); m4 = fmaxf(m4, m6);
        const float v = fmaxf(m0, m4);
        unsigned c[16];
#pragma unroll
        for (int j = 0; j < 16; j++)
            c[j] = (dist[j] == v) ? (unsigned)(j * FT + tid) : 0xffffffffu;
#pragma unroll
        for (int st = 1; st < 16; st <<= 1)
#pragma unroll
            for (int j = 0; j < 16; j += 2 * st)
                c[j] = min(c[j], c[j + st]);
        unsigned vi = c[0];

        unsigned vb = __float_as_uint(v);
        unsigned M  = __reduce_max_sync(FULLMASK, vb);
        unsigned cand = (vb == M) ? vi : 0xffffffffu;
        unsigned mi = __reduce_min_sync(FULLMASK, cand);
        const int slot = (k & 1) << 4;
        if (lane == 0) { sv[slot + wid] = M; sidx[slot + wid] = mi; }
        __syncthreads();
        int l = slot + (lane & 15);
        unsigned pv = sv[l], pi = sidx[l];
        unsigned M2 = __reduce_max_sync(FULLMASK, pv);
        unsigned cand2 = (pv == M2) ? pi : 0xffffffffu;
        unsigned far = __reduce_min_sync(FULLMASK, cand2);
        qx = sx[far]; qy = sy[far]; qz = sz[far];
        if (tid == 0) {
            g_center[b * NG + k] = make_float4(qx, qy, qz, sumsq3(qx, qy, qz));
            if (out_size >= C_OFF + C_SZ) {
                out[C_OFF + (size_t)(b * NG + k) * 3 + 0] = qx;
                out[C_OFF + (size_t)(b * NG + k) * 3 + 1] = qy;
                out[C_OFF + (size_t)(b * NG + k) * 3 + 2] = qz;
            }
            if ((k & 7) == 7 || k == NG - 1)
                rel_store(&g_prog[b], k);     // release: orders center stores
        }
    }
}

// ---------------------------------------------------------------------------
// sort role: waits pts_ready, 256-bin counting sort by x, publishes sort_done.
// Within-bin order nondeterministic -- harmless (selection is order-invariant).
// ---------------------------------------------------------------------------
__device__ void sort_role(int b) {
    const int tid = threadIdx.x;
    const int lane = tid & 31, wid = tid >> 5;

    if (tid == 0) { while (atomicAdd(&g_pts_ready[b], 0) == 0) __nanosleep(1000); }
    __syncthreads();

    const float4* pts = g_pts + b * NPTS;
    float xv[16];
    float lmin = PINF, lmax = -PINF;
#pragma unroll
    for (int j = 0; j < 16; j++) {
        xv[j] = pts[j * FT + tid].x;
        lmin = fminf(lmin, xv[j]); lmax = fmaxf(lmax, xv[j]);
    }
#pragma unroll
    for (int off = 16; off > 0; off >>= 1) {
        lmin = fminf(lmin, __shfl_down_sync(FULLMASK, lmin, off));
        lmax = fmaxf(lmax, __shfl_down_sync(FULLMASK, lmax, off));
    }
    if (lane == 0) { s_red[wid] = lmin; s_red[32 + wid] = lmax; }
    if (tid < NSLAB) s_hist[tid] = 0;
    __syncthreads();
    if (tid < 32) {
        float a = (tid < 16) ? s_red[tid] : PINF;
        float c = (tid < 16) ? s_red[32 + tid] : -PINF;
#pragma unroll
        for (int off = 16; off > 0; off >>= 1) {
            a = fminf(a, __shfl_down_sync(FULLMASK, a, off));
            c = fmaxf(c, __shfl_down_sync(FULLMASK, c, off));
        }
        if (tid == 0) { s_mm[0] = a; s_mm[1] = c; }
    }
    __syncthreads();
    const float xmin = s_mm[0];
    const float scale = 255.0f / fmaxf(s_mm[1] - xmin, 1e-20f);
    int bins[16];
#pragma unroll
    for (int j = 0; j < 16; j++) {
        int bn = (int)((xv[j] - xmin) * scale);
        bins[j] = bn < 0 ? 0 : (bn > 255 ? 255 : bn);
        atomicAdd(&s_hist[bins[j]], 1);
    }
    __syncthreads();
    if (tid < 32) {
        int v[8], s = 0;
#pragma unroll
        for (int r = 0; r < 8; r++) { v[r] = s_hist[tid * 8 + r]; s += v[r]; }
        int inc = s;
#pragma unroll
        for (int off = 1; off < 32; off <<= 1) {
            int n = __shfl_up_sync(FULLMASK, inc, off);
            if (tid >= off) inc += n;
        }
        int run = inc - s;
#pragma unroll
        for (int r = 0; r < 8; r++) { int t = v[r]; s_hist[tid * 8 + r] = run; run += t; }
    }
    __syncthreads();
#pragma unroll
    for (int j = 0; j < 16; j++) {
        int i = j * FT + tid;
        int pos = atomicAdd(&s_hist[bins[j]], 1);
        g_spts[b * NPTS + pos] = pts[i];
        g_sidx[b * NPTS + pos] = i;
    }
    __threadfence();
    __syncthreads();
    if (tid < NSLAB) {
        float mn = PINF, mx = -PINF;
#pragma unroll 8
        for (int r = 0; r < 32; r++) {
            float x = g_spts[b * NPTS + tid * 32 + r].x;
            mn = fminf(mn, x); mx = fmaxf(mx, x);
        }
        g_slab[b * NSLAB + tid] = make_float2(mn, mx);
    }
    __threadfence();
    __syncthreads();
    if (tid == 0) atomicExch(&g_sort_done[b], 1);
}

// ---------------------------------------------------------------------------
// kNN role: 32 CTAs total = 4 per batch; CTA = 16 warps = 8 pair-groups;
// 16 rounds in center-index order, each pair acquire-polls g_prog. Slab-pruned
// outward scan + buffered bitonic merges (exact; identical to R9 passing).
// ---------------------------------------------------------------------------
__device__ __forceinline__ float ref_dist(float4 c, float x, float y, float z, float p2) {
    float dot = __fmul_rn(c.x, x);
    dot = __fmaf_rn(c.y, y, dot);
    dot = __fmaf_rn(c.z, z, dot);
    return __fsub_rn(__fadd_rn(c.w, p2), __fmul_rn(2.0f, dot));
}
__device__ __forceinline__ bool key_less(float ad, int ai, float bd, int bi) {
    return (ad < bd) || (ad == bd && ai < bi);
}
__device__ __forceinline__ void sort32(float& Sd, int& Si, int lane) {
#pragma unroll
    for (int k = 2; k <= 32; k <<= 1) {
        const bool dd = (lane & k) != 0;
#pragma unroll
        for (int j = k >> 1; j > 0; j >>= 1) {
            float od = __shfl_xor_sync(FULLMASK, Sd, j);
            int   oi = __shfl_xor_sync(FULLMASK, Si, j);
            bool lower = key_less(od, oi, Sd, Si);
            bool takeSmaller = (((lane & j) == 0) != dd);
            if (lower == takeSmaller) { Sd = od; Si = oi; }
        }
    }
}
__device__ __forceinline__ void bitonic_cleanup(float& Sd, int& Si, int lane) {
#pragma unroll
    for (int j = 16; j > 0; j >>= 1) {
        float od = __shfl_xor_sync(FULLMASK, Sd, j);
        int   oi = __shfl_xor_sync(FULLMASK, Si, j);
        bool lower = key_less(od, oi, Sd, Si);
        bool takeSmaller = ((lane & j) == 0);
        if (lower == takeSmaller) { Sd = od; Si = oi; }
    }
}

__device__ void knn_role(const float* __restrict__ xyz, float* __restrict__ out,
                         int out_size, int kc) {
    const int tid  = threadIdx.x;
    const int lane = tid & 31;
    const int w    = tid >> 5;            // warp in CTA, 0..15
    const int gib  = w >> 1;              // pair, 0..7
    const int role = w & 1;
    const int b    = kc >> 2;             // 4 CTAs per batch
    const int cib  = kc & 3;
    const unsigned lmlt = (1u << lane) - 1u;

    if (lane == 0) { while (atomicAdd(&g_sort_done[b], 0) == 0) __nanosleep(1000); }
    __syncwarp();
    if (tid < NSLAB) k_slab[tid] = g_slab[b * NSLAB + tid];
    __syncthreads();

    const float4* sp = g_spts + b * NPTS;
    const int*    si = g_sidx + b * NPTS;

    for (int t = 0; t < 16; t++) {
        const int k_id = t * 32 + cib * 8 + gib;
        const int grp  = b * NG + k_id;
        if (lane == 0) { while (acq_load(&g_prog[b]) < k_id) __nanosleep(400); }
        __syncwarp();
        const float4 c = __ldcg(&g_center[grp]);   // L2-fresh (bypass L1)

        int cnt = 0;
#pragma unroll
        for (int r = 0; r < 8; r++) {
            float2 sl = k_slab[r * 32 + lane];
            cnt += __popc(__ballot_sync(FULLMASK, sl.x <= c.x));
        }
        const int s0 = cnt > 0 ? cnt - 1 : 0;

        float Sd = PINF; int Si = 0x7fffffff;
        float Td = PINF; int Ti = 0x7fffffff;
        int bcnt = 0;

        auto merge_buf = [&](int take) {
            float bd = (lane < take) ? k_bufD[w][lane] : PINF;
            int   bi = (lane < take) ? k_bufI[w][lane] : 0x7fffffff;
            sort32(bd, bi, lane);
            float rd = __shfl_sync(FULLMASK, bd, 31 - lane);
            int   ri = __shfl_sync(FULLMASK, bi, 31 - lane);
            if (key_less(rd, ri, Sd, Si)) { Sd = rd; Si = ri; }
            bitonic_cleanup(Sd, Si, lane);
            int rem = bcnt - take;
            if (lane < rem) { k_bufD[w][lane] = k_bufD[w][32 + lane]; k_bufI[w][lane] = k_bufI[w][32 + lane]; }
            bcnt = rem;
            Td = __shfl_sync(FULLMASK, Sd, 31);
            Ti = __shfl_sync(FULLMASK, Si, 31);
        };

        auto process = [&](int s) {
            float2 sl = k_slab[s];
            float lb = fmaxf(fmaxf(sl.x - c.x, c.x - sl.y), 0.0f);
            if (__fmul_rn(__fmul_rn(lb, lb), 0.98f) > Td) return;   // safe-margin skip
            const int base = s * 32;
            float4 p = sp[base + lane];
            int    oi = si[base + lane];
            float d = ref_dist(c, p.x, p.y, p.z, p.w);
            bool qf = key_less(d, oi, Td, Ti);
            unsigned m = __ballot_sync(FULLMASK, qf);
            if (m) {
                int pos = bcnt + __popc(m & lmlt);
                if (qf) { k_bufD[w][pos] = d; k_bufI[w][pos] = oi; }
                bcnt += __popc(m);
                if (bcnt >= 32) merge_buf(32);
            }
        };

        if (role == 0) { for (int s = s0; s < NSLAB; s++) process(s); }
        else           { for (int s = s0 - 1; s >= 0; s--) process(s); }
        if (bcnt > 0) merge_buf(bcnt);

        if (role == 1) { k_mD[gib][lane] = Sd; k_mI[gib][lane] = Si; }
        asm volatile("bar.sync %0, %1;" :: "r"(gib + 1), "r"(64) : "memory");
        if (role == 0) {
            float rd = k_mD[gib][31 - lane];
            int   ri = k_mI[gib][31 - lane];
            if (key_less(rd, ri, Sd, Si)) { Sd = rd; Si = ri; }
            bitonic_cleanup(Sd, Si, lane);

            const int n = Si;
            float4 pw = g_pts[b * NPTS + n];
            const float* pb = xyz + ((size_t)b * NPTS + n) * CDIM;
            float e0 = pb[3], e1 = pb[4], e2 = pb[5];
            float2 w0 = make_float2(pw.x - c.x, pw.y - c.y);
            float2 w1 = make_float2(pw.z - c.z, e0);
            float2 w2 = make_float2(e1, e2);
            float2* ob = (float2*)out + ((size_t)grp * GS + lane) * 3;
            ob[0] = w0; ob[1] = w1; ob[2] = w2;
            if (out_size >= I_OFF + I_SZ)
                out[I_OFF + (size_t)grp * GS + lane] = (float)n;
        }
        asm volatile("bar.sync %0, %1;" :: "r"(gib + 1), "r"(64) : "memory");
    }
}

// ---------------------------------------------------------------------------
__global__ void init_kernel() {
    int i = threadIdx.x;
    if (i < BATCH) { g_prog[i] = -1; g_pts_ready[i] = 0; g_sort_done[i] = 0; }
}

extern __shared__ char dyn_smem[];
__global__ void __launch_bounds__(FT, 1)
fused_kernel(const float* __restrict__ xyz, float* __restrict__ out, int out_size) {
    const int bid = blockIdx.x;
    if (bid < 8)       fps_role(xyz, out, out_size, bid, dyn_smem);
    else if (bid < 16) sort_role(bid - 8);
    else               knn_role(xyz, out, out_size, bid - 16);
}

extern "C" void kernel_launch(void* const* d_in, const int* in_sizes, int n_in,
                              void* d_out, int out_size) {
    const float* xyz = (const float*)d_in[0];
    float* out = (float*)d_out;
    (void)in_sizes; (void)n_in;

    cudaFuncSetAttribute(fused_kernel, cudaFuncAttributeMaxDynamicSharedMemorySize,
                         (int)FPS_SMEM);
    init_kernel<<<1, 32>>>();
    fused_kernel<<<48, FT, FPS_SMEM>>>(xyz, out, out_size);
}

// round 12
// speedup vs baseline: 1.6794x; 1.6794x over previous
#include <cuda_runtime.h>
#include <cstdint>
#include <cstddef>

#define BATCH   8
#define NPTS    8192
#define CDIM    6
#define NG      512
#define GS      32
#define NSLAB   256
#define FULLMASK 0xffffffffu
#define PINF    __int_as_float(0x7f800000)

// output layout: neighborhood, center, idx (flattened tuple order, all f32)
#define NB_SZ  (BATCH * NG * GS * CDIM)   // 786432
#define C_OFF  (NB_SZ)
#define C_SZ   (BATCH * NG * 3)           // 12288
#define I_OFF  (C_OFF + C_SZ)             // 798720
#define I_SZ   (BATCH * NG * GS)          // 131072

// scratch (no allocations allowed -> __device__ globals)
__device__ float4 g_pts[BATCH * NPTS];    // original order: (x, y, z, |p|^2)
__device__ float4 g_spts[BATCH * NPTS];   // x-sorted order
__device__ int    g_sidx[BATCH * NPTS];   // sorted pos -> original index
__device__ float2 g_slab[BATCH * NSLAB];  // per-32-point slab (xmin, xmax)
__device__ float4 g_center[BATCH * NG];   // (cx, cy, cz, |c|^2)
__device__ int    g_prog[BATCH];          // highest published center index
__device__ int    g_pts_ready[BATCH];
__device__ int    g_sort_done[BATCH];

// ---------------------------------------------------------------------------
// packed f32x2 helpers (FFMA2; per-component RN rounding identical to scalar)
// ---------------------------------------------------------------------------
__device__ __forceinline__ unsigned long long pk2(float lo, float hi) {
    unsigned long long r;
    asm("mov.b64 %0, {%1, %2};" : "=l"(r)
        : "r"(__float_as_uint(lo)), "r"(__float_as_uint(hi)));
    return r;
}
__device__ __forceinline__ void upk2(unsigned long long v, float& lo, float& hi) {
    unsigned a, b;
    asm("mov.b64 {%0, %1}, %2;" : "=r"(a), "=r"(b) : "l"(v));
    lo = __uint_as_float(a); hi = __uint_as_float(b);
}
__device__ __forceinline__ unsigned long long add2(unsigned long long a, unsigned long long b) {
    unsigned long long r;
    asm("add.rn.f32x2 %0, %1, %2;" : "=l"(r) : "l"(a), "l"(b));
    return r;
}
__device__ __forceinline__ unsigned long long mul2(unsigned long long a, unsigned long long b) {
    unsigned long long r;
    asm("mul.rn.f32x2 %0, %1, %2;" : "=l"(r) : "l"(a), "l"(b));
    return r;
}
__device__ __forceinline__ unsigned long long fma2(unsigned long long a, unsigned long long b,
                                                   unsigned long long c) {
    unsigned long long r;
    asm("fma.rn.f32x2 %0, %1, %2, %3;" : "=l"(r) : "l"(a), "l"(b), "l"(c));
    return r;
}

__device__ __forceinline__ float sumsq3(float x, float y, float z) {
    float t = __fmul_rn(x, x);
    t = __fmaf_rn(y, y, t);
    t = __fmaf_rn(z, z, t);
    return t;
}

#define FT 512
#define FPS_SMEM ((size_t)(3 * NPTS) * sizeof(float) + 64 * sizeof(unsigned))

// static shared (roles use disjoint subsets)
__shared__ float  s_red[64];
__shared__ int    s_hist[NSLAB];
__shared__ float  s_mm[2];
__shared__ float2 k_slab[NSLAB];
__shared__ float  k_bufD[16][64];
__shared__ int    k_bufI[16][64];
__shared__ float  k_mD[8][32];
__shared__ int    k_mI[8][32];

// ---------------------------------------------------------------------------
// FPS role: EXACT R9 code (monolithic 512-step loop, serial in-loop argmax,
// fence+atomicExch publish every 8 steps). Proven at 316us total.
// ---------------------------------------------------------------------------
__device__ void fps_role(const float* __restrict__ xyz, float* __restrict__ out,
                         int out_size, int b, char* dsm) {
    const int tid = threadIdx.x;
    float* sx = (float*)dsm;
    float* sy = sx + NPTS;
    float* sz = sx + 2 * NPTS;
    unsigned* sv   = (unsigned*)(sx + 3 * NPTS);
    unsigned* sidx = sv + 32;

    const float* base = xyz + (size_t)b * NPTS * CDIM;
    unsigned long long pxx[8], pyy[8], pzz[8];
    float dist[16];
    float prx = 0.f, pry = 0.f, prz = 0.f;
#pragma unroll
    for (int j = 0; j < 16; j++) {
        int i = j * FT + tid;
        float x = base[i * CDIM + 0];
        float y = base[i * CDIM + 1];
        float z = base[i * CDIM + 2];
        sx[i] = x; sy[i] = y; sz[i] = z;
        g_pts[b * NPTS + i] = make_float4(x, y, z, sumsq3(x, y, z));
        dist[j] = PINF;
        if ((j & 1) == 0) { prx = x; pry = y; prz = z; }
        else {
            pxx[j >> 1] = pk2(prx, x);
            pyy[j >> 1] = pk2(pry, y);
            pzz[j >> 1] = pk2(prz, z);
        }
    }
    __threadfence();                       // make g_pts visible before flag
    __syncthreads();
    if (tid == 0) atomicExch(&g_pts_ready[b], 1);

    float qx = sx[0], qy = sy[0], qz = sz[0];
    if (tid == 0) {
        g_center[b * NG] = make_float4(qx, qy, qz, sumsq3(qx, qy, qz));
        if (out_size >= C_OFF + C_SZ) {
            out[C_OFF + (size_t)(b * NG) * 3 + 0] = qx;
            out[C_OFF + (size_t)(b * NG) * 3 + 1] = qy;
            out[C_OFF + (size_t)(b * NG) * 3 + 2] = qz;
        }
    }

    const int lane = tid & 31, wid = tid >> 5;
    for (int k = 1; k < NG; k++) {
        const unsigned long long nqx2 = pk2(-qx, -qx);
        const unsigned long long nqy2 = pk2(-qy, -qy);
        const unsigned long long nqz2 = pk2(-qz, -qz);
        float v = -1.0f; unsigned vi = 0;
#pragma unroll
        for (int j = 0; j < 8; j++) {
            unsigned long long dx2 = add2(pxx[j], nqx2);
            unsigned long long dy2 = add2(pyy[j], nqy2);
            unsigned long long dz2 = add2(pzz[j], nqz2);
            unsigned long long t  = mul2(dx2, dx2);
            t = fma2(dy2, dy2, t);
            t = fma2(dz2, dz2, t);
            float dlo, dhi; upk2(t, dlo, dhi);
            float nd = fminf(dist[2 * j], dlo);
            dist[2 * j] = nd;
            if (nd > v) { v = nd; vi = (unsigned)((2 * j) * FT + tid); }
            nd = fminf(dist[2 * j + 1], dhi);
            dist[2 * j + 1] = nd;
            if (nd > v) { v = nd; vi = (unsigned)((2 * j + 1) * FT + tid); }
        }
        unsigned vb = __float_as_uint(v);
        unsigned M  = __reduce_max_sync(FULLMASK, vb);
        unsigned cand = (vb == M) ? vi : 0xffffffffu;
        unsigned mi = __reduce_min_sync(FULLMASK, cand);
        const int slot = (k & 1) << 4;
        if (lane == 0) { sv[slot + wid] = M; sidx[slot + wid] = mi; }
        __syncthreads();
        int l = slot + (lane & 15);
        unsigned pv = sv[l], pi = sidx[l];
        unsigned M2 = __reduce_max_sync(FULLMASK, pv);
        unsigned cand2 = (pv == M2) ? pi : 0xffffffffu;
        unsigned far = __reduce_min_sync(FULLMASK, cand2);
        qx = sx[far]; qy = sy[far]; qz = sz[far];
        if (tid == 0) {
            g_center[b * NG + k] = make_float4(qx, qy, qz, sumsq3(qx, qy, qz));
            if (out_size >= C_OFF + C_SZ) {
                out[C_OFF + (size_t)(b * NG + k) * 3 + 0] = qx;
                out[C_OFF + (size_t)(b * NG + k) * 3 + 1] = qy;
                out[C_OFF + (size_t)(b * NG + k) * 3 + 2] = qz;
            }
            if ((k & 7) == 7 || k == NG - 1) {
                __threadfence();                 // centers -> L2 before progress
                atomicExch(&g_prog[b], k);
            }
        }
    }
}

// ---------------------------------------------------------------------------
// sort role: EXACT R9 code.
// ---------------------------------------------------------------------------
__device__ void sort_role(int b) {
    const int tid = threadIdx.x;
    const int lane = tid & 31, wid = tid >> 5;

    if (tid == 0) { while (atomicAdd(&g_pts_ready[b], 0) == 0) __nanosleep(1000); }
    __syncthreads();

    const float4* pts = g_pts + b * NPTS;
    float xv[16];
    float lmin = PINF, lmax = -PINF;
#pragma unroll
    for (int j = 0; j < 16; j++) {
        xv[j] = pts[j * FT + tid].x;
        lmin = fminf(lmin, xv[j]); lmax = fmaxf(lmax, xv[j]);
    }
#pragma unroll
    for (int off = 16; off > 0; off >>= 1) {
        lmin = fminf(lmin, __shfl_down_sync(FULLMASK, lmin, off));
        lmax = fmaxf(lmax, __shfl_down_sync(FULLMASK, lmax, off));
    }
    if (lane == 0) { s_red[wid] = lmin; s_red[32 + wid] = lmax; }
    if (tid < NSLAB) s_hist[tid] = 0;
    __syncthreads();
    if (tid < 32) {
        float a = (tid < 16) ? s_red[tid] : PINF;
        float c = (tid < 16) ? s_red[32 + tid] : -PINF;
#pragma unroll
        for (int off = 16; off > 0; off >>= 1) {
            a = fminf(a, __shfl_down_sync(FULLMASK, a, off));
            c = fmaxf(c, __shfl_down_sync(FULLMASK, c, off));
        }
        if (tid == 0) { s_mm[0] = a; s_mm[1] = c; }
    }
    __syncthreads();
    const float xmin = s_mm[0];
    const float scale = 255.0f / fmaxf(s_mm[1] - xmin, 1e-20f);
    int bins[16];
#pragma unroll
    for (int j = 0; j < 16; j++) {
        int bn = (int)((xv[j] - xmin) * scale);
        bins[j] = bn < 0 ? 0 : (bn > 255 ? 255 : bn);
        atomicAdd(&s_hist[bins[j]], 1);
    }
    __syncthreads();
    if (tid < 32) {
        int v[8], s = 0;
#pragma unroll
        for (int r = 0; r < 8; r++) { v[r] = s_hist[tid * 8 + r]; s += v[r]; }
        int inc = s;
#pragma unroll
        for (int off = 1; off < 32; off <<= 1) {
            int n = __shfl_up_sync(FULLMASK, inc, off);
            if (tid >= off) inc += n;
        }
        int run = inc - s;
#pragma unroll
        for (int r = 0; r < 8; r++) { int t = v[r]; s_hist[tid * 8 + r] = run; run += t; }
    }
    __syncthreads();
#pragma unroll
    for (int j = 0; j < 16; j++) {
        int i = j * FT + tid;
        int pos = atomicAdd(&s_hist[bins[j]], 1);
        g_spts[b * NPTS + pos] = pts[i];
        g_sidx[b * NPTS + pos] = i;
    }
    __threadfence();
    __syncthreads();
    if (tid < NSLAB) {
        float mn = PINF, mx = -PINF;
#pragma unroll 8
        for (int r = 0; r < 32; r++) {
            float x = g_spts[b * NPTS + tid * 32 + r].x;
            mn = fminf(mn, x); mx = fmaxf(mx, x);
        }
        g_slab[b * NSLAB + tid] = make_float2(mn, mx);
    }
    __threadfence();
    __syncthreads();
    if (tid == 0) atomicExch(&g_sort_done[b], 1);
}

// ---------------------------------------------------------------------------
// kNN role: EXACT R9 code except round count — 64 CTAs total = 8 per batch,
// 8 rounds per pair (k_id = t*64 + cib*8 + gib). Exact under (d2, idx).
// ---------------------------------------------------------------------------
__device__ __forceinline__ float ref_dist(float4 c, float x, float y, float z, float p2) {
    float dot = __fmul_rn(c.x, x);
    dot = __fmaf_rn(c.y, y, dot);
    dot = __fmaf_rn(c.z, z, dot);
    return __fsub_rn(__fadd_rn(c.w, p2), __fmul_rn(2.0f, dot));
}
__device__ __forceinline__ bool key_less(float ad, int ai, float bd, int bi) {
    return (ad < bd) || (ad == bd && ai < bi);
}
__device__ __forceinline__ void sort32(float& Sd, int& Si, int lane) {
#pragma unroll
    for (int k = 2; k <= 32; k <<= 1) {
        const bool dd = (lane & k) != 0;
#pragma unroll
        for (int j = k >> 1; j > 0; j >>= 1) {
            float od = __shfl_xor_sync(FULLMASK, Sd, j);
            int   oi = __shfl_xor_sync(FULLMASK, Si, j);
            bool lower = key_less(od, oi, Sd, Si);
            bool takeSmaller = (((lane & j) == 0) != dd);
            if (lower == takeSmaller) { Sd = od; Si = oi; }
        }
    }
}
__device__ __forceinline__ void bitonic_cleanup(float& Sd, int& Si, int lane) {
#pragma unroll
    for (int j = 16; j > 0; j >>= 1) {
        float od = __shfl_xor_sync(FULLMASK, Sd, j);
        int   oi = __shfl_xor_sync(FULLMASK, Si, j);
        bool lower = key_less(od, oi, Sd, Si);
        bool takeSmaller = ((lane & j) == 0);
        if (lower == takeSmaller) { Sd = od; Si = oi; }
    }
}

__device__ void knn_role(const float* __restrict__ xyz, float* __restrict__ out,
                         int out_size, int kc) {
    const int tid  = threadIdx.x;
    const int lane = tid & 31;
    const int w    = tid >> 5;            // warp in CTA, 0..15
    const int gib  = w >> 1;              // pair, 0..7
    const int role = w & 1;
    const int b    = kc >> 3;             // 8 CTAs per batch
    const int cib  = kc & 7;
    const unsigned lmlt = (1u << lane) - 1u;

    if (lane == 0) { while (atomicAdd(&g_sort_done[b], 0) == 0) __nanosleep(1000); }
    __syncwarp();
    if (tid < NSLAB) k_slab[tid] = g_slab[b * NSLAB + tid];
    __syncthreads();

    const float4* sp = g_spts + b * NPTS;
    const int*    si = g_sidx + b * NPTS;

    for (int t = 0; t < 8; t++) {
        const int k_id = t * 64 + cib * 8 + gib;
        const int grp  = b * NG + k_id;
        if (lane == 0) { while (atomicAdd(&g_prog[b], 0) < k_id) __nanosleep(400); }
        __syncwarp();
        const float4 c = __ldcg(&g_center[grp]);   // L2-fresh (bypass L1)

        int cnt = 0;
#pragma unroll
        for (int r = 0; r < 8; r++) {
            float2 sl = k_slab[r * 32 + lane];
            cnt += __popc(__ballot_sync(FULLMASK, sl.x <= c.x));
        }
        const int s0 = cnt > 0 ? cnt - 1 : 0;

        float Sd = PINF; int Si = 0x7fffffff;
        float Td = PINF; int Ti = 0x7fffffff;
        int bcnt = 0;

        auto merge_buf = [&](int take) {
            float bd = (lane < take) ? k_bufD[w][lane] : PINF;
            int   bi = (lane < take) ? k_bufI[w][lane] : 0x7fffffff;
            sort32(bd, bi, lane);
            float rd = __shfl_sync(FULLMASK, bd, 31 - lane);
            int   ri = __shfl_sync(FULLMASK, bi, 31 - lane);
            if (key_less(rd, ri, Sd, Si)) { Sd = rd; Si = ri; }
            bitonic_cleanup(Sd, Si, lane);
            int rem = bcnt - take;
            if (lane < rem) { k_bufD[w][lane] = k_bufD[w][32 + lane]; k_bufI[w][lane] = k_bufI[w][32 + lane]; }
            bcnt = rem;
            Td = __shfl_sync(FULLMASK, Sd, 31);
            Ti = __shfl_sync(FULLMASK, Si, 31);
        };

        auto process = [&](int s) {
            float2 sl = k_slab[s];
            float lb = fmaxf(fmaxf(sl.x - c.x, c.x - sl.y), 0.0f);
            if (__fmul_rn(__fmul_rn(lb, lb), 0.98f) > Td) return;   // safe-margin skip
            const int base = s * 32;
            float4 p = sp[base + lane];
            int    oi = si[base + lane];
            float d = ref_dist(c, p.x, p.y, p.z, p.w);
            bool qf = key_less(d, oi, Td, Ti);
            unsigned m = __ballot_sync(FULLMASK, qf);
            if (m) {
                int pos = bcnt + __popc(m & lmlt);
                if (qf) { k_bufD[w][pos] = d; k_bufI[w][pos] = oi; }
                bcnt += __popc(m);
                if (bcnt >= 32) merge_buf(32);
            }
        };

        if (role == 0) { for (int s = s0; s < NSLAB; s++) process(s); }
        else           { for (int s = s0 - 1; s >= 0; s--) process(s); }
        if (bcnt > 0) merge_buf(bcnt);

        if (role == 1) { k_mD[gib][lane] = Sd; k_mI[gib][lane] = Si; }
        asm volatile("bar.sync %0, %1;" :: "r"(gib + 1), "r"(64) : "memory");
        if (role == 0) {
            float rd = k_mD[gib][31 - lane];
            int   ri = k_mI[gib][31 - lane];
            if (key_less(rd, ri, Sd, Si)) { Sd = rd; Si = ri; }
            bitonic_cleanup(Sd, Si, lane);

            const int n = Si;
            float4 pw = g_pts[b * NPTS + n];
            const float* pb = xyz + ((size_t)b * NPTS + n) * CDIM;
            float e0 = pb[3], e1 = pb[4], e2 = pb[5];
            float2 w0 = make_float2(pw.x - c.x, pw.y - c.y);
            float2 w1 = make_float2(pw.z - c.z, e0);
            float2 w2 = make_float2(e1, e2);
            float2* ob = (float2*)out + ((size_t)grp * GS + lane) * 3;
            ob[0] = w0; ob[1] = w1; ob[2] = w2;
            if (out_size >= I_OFF + I_SZ)
                out[I_OFF + (size_t)grp * GS + lane] = (float)n;
        }
        asm volatile("bar.sync %0, %1;" :: "r"(gib + 1), "r"(64) : "memory");
    }
}

// ---------------------------------------------------------------------------
__global__ void init_kernel() {
    int i = threadIdx.x;
    if (i < BATCH) { g_prog[i] = -1; g_pts_ready[i] = 0; g_sort_done[i] = 0; }
}

extern __shared__ char dyn_smem[];
__global__ void __launch_bounds__(FT, 1)
fused_kernel(const float* __restrict__ xyz, float* __restrict__ out, int out_size) {
    const int bid = blockIdx.x;
    if (bid < 8)       fps_role(xyz, out, out_size, bid, dyn_smem);
    else if (bid < 16) sort_role(bid - 8);
    else               knn_role(xyz, out, out_size, bid - 16);
}

extern "C" void kernel_launch(void* const* d_in, const int* in_sizes, int n_in,
                              void* d_out, int out_size) {
    const float* xyz = (const float*)d_in[0];
    float* out = (float*)d_out;
    (void)in_sizes; (void)n_in;

    cudaFuncSetAttribute(fused_kernel, cudaFuncAttributeMaxDynamicSharedMemorySize,
                         (int)FPS_SMEM);
    init_kernel<<<1, 32>>>();
    fused_kernel<<<80, FT, FPS_SMEM>>>(xyz, out, out_size);
}

// round 13
// speedup vs baseline: 1.7506x; 1.0424x over previous
#include <cuda_runtime.h>
#include <cstdint>
#include <cstddef>

#define BATCH   8
#define NPTS    8192
#define CDIM    6
#define NG      512
#define GS      32
#define NSLAB   256
#define FULLMASK 0xffffffffu
#define PINF    __int_as_float(0x7f800000)

// output layout: neighborhood, center, idx (flattened tuple order, all f32)
#define NB_SZ  (BATCH * NG * GS * CDIM)   // 786432
#define C_OFF  (NB_SZ)
#define C_SZ   (BATCH * NG * 3)           // 12288
#define I_OFF  (C_OFF + C_SZ)             // 798720
#define I_SZ   (BATCH * NG * GS)          // 131072

// scratch (no allocations allowed -> __device__ globals)
__device__ float4 g_pts[BATCH * NPTS];    // original order: (x, y, z, |p|^2)
__device__ float4 g_spts[BATCH * NPTS];   // x-sorted order
__device__ int    g_sidx[BATCH * NPTS];   // sorted pos -> original index
__device__ float2 g_slab[BATCH * NSLAB];  // per-32-point slab (xmin, xmax)
__device__ float4 g_center[BATCH * NG];   // (cx, cy, cz, |c|^2)
__device__ int    g_prog[BATCH];          // highest published center index
__device__ int    g_pts_ready[BATCH];
__device__ int    g_sort_done[BATCH];

// ---------------------------------------------------------------------------
// packed f32x2 helpers (FFMA2; per-component RN rounding identical to scalar)
// ---------------------------------------------------------------------------
__device__ __forceinline__ unsigned long long pk2(float lo, float hi) {
    unsigned long long r;
    asm("mov.b64 %0, {%1, %2};" : "=l"(r)
        : "r"(__float_as_uint(lo)), "r"(__float_as_uint(hi)));
    return r;
}
__device__ __forceinline__ void upk2(unsigned long long v, float& lo, float& hi) {
    unsigned a, b;
    asm("mov.b64 {%0, %1}, %2;" : "=r"(a), "=r"(b) : "l"(v));
    lo = __uint_as_float(a); hi = __uint_as_float(b);
}
__device__ __forceinline__ unsigned long long add2(unsigned long long a, unsigned long long b) {
    unsigned long long r;
    asm("add.rn.f32x2 %0, %1, %2;" : "=l"(r) : "l"(a), "l"(b));
    return r;
}
__device__ __forceinline__ unsigned long long mul2(unsigned long long a, unsigned long long b) {
    unsigned long long r;
    asm("mul.rn.f32x2 %0, %1, %2;" : "=l"(r) : "l"(a), "l"(b));
    return r;
}
__device__ __forceinline__ unsigned long long fma2(unsigned long long a, unsigned long long b,
                                                   unsigned long long c) {
    unsigned long long r;
    asm("fma.rn.f32x2 %0, %1, %2, %3;" : "=l"(r) : "l"(a), "l"(b), "l"(c));
    return r;
}

__device__ __forceinline__ float sumsq3(float x, float y, float z) {
    float t = __fmul_rn(x, x);
    t = __fmaf_rn(y, y, t);
    t = __fmaf_rn(z, z, t);
    return t;
}

// release/acquire progress protocol: tid0 performed ALL center stores itself,
// so st.release.gpu orders them without a full MEMBAR drain; consumers'
// ld.acquire.gpu orders their subsequent __ldcg center reads.
__device__ __forceinline__ void rel_store(int* p, int v) {
    asm volatile("st.release.gpu.s32 [%0], %1;" :: "l"(p), "r"(v) : "memory");
}
__device__ __forceinline__ int acq_load(const int* p) {
    int v;
    asm volatile("ld.acquire.gpu.s32 %0, [%1];" : "=r"(v) : "l"(p) : "memory");
    return v;
}

#define FT 512
#define FPS_SMEM ((size_t)(3 * NPTS) * sizeof(float) + 64 * sizeof(unsigned))

// static shared (roles use disjoint subsets)
__shared__ float  s_red[64];
__shared__ int    s_hist[NSLAB];
__shared__ float  s_mm[2];
__shared__ float2 k_slab[NSLAB];
__shared__ float  k_bufD[16][64];
__shared__ int    k_bufI[16][64];
__shared__ float  k_mD[8][32];
__shared__ int    k_mI[8][32];

// ---------------------------------------------------------------------------
// FPS role: R12 code with ONE change — progress publish is st.release.gpu
// instead of __threadfence + atomicExch (removes 64 MEMBAR.GPU stalls that
// the whole CTA inherits at the next __syncthreads).
// ---------------------------------------------------------------------------
__device__ void fps_role(const float* __restrict__ xyz, float* __restrict__ out,
                         int out_size, int b, char* dsm) {
    const int tid = threadIdx.x;
    float* sx = (float*)dsm;
    float* sy = sx + NPTS;
    float* sz = sx + 2 * NPTS;
    unsigned* sv   = (unsigned*)(sx + 3 * NPTS);
    unsigned* sidx = sv + 32;

    const float* base = xyz + (size_t)b * NPTS * CDIM;
    unsigned long long pxx[8], pyy[8], pzz[8];
    float dist[16];
    float prx = 0.f, pry = 0.f, prz = 0.f;
#pragma unroll
    for (int j = 0; j < 16; j++) {
        int i = j * FT + tid;
        float x = base[i * CDIM + 0];
        float y = base[i * CDIM + 1];
        float z = base[i * CDIM + 2];
        sx[i] = x; sy[i] = y; sz[i] = z;
        g_pts[b * NPTS + i] = make_float4(x, y, z, sumsq3(x, y, z));
        dist[j] = PINF;
        if ((j & 1) == 0) { prx = x; pry = y; prz = z; }
        else {
            pxx[j >> 1] = pk2(prx, x);
            pyy[j >> 1] = pk2(pry, y);
            pzz[j >> 1] = pk2(prz, z);
        }
    }
    __threadfence();                       // one-time: g_pts written by ALL threads
    __syncthreads();
    if (tid == 0) atomicExch(&g_pts_ready[b], 1);

    float qx = sx[0], qy = sy[0], qz = sz[0];
    if (tid == 0) {
        g_center[b * NG] = make_float4(qx, qy, qz, sumsq3(qx, qy, qz));
        if (out_size >= C_OFF + C_SZ) {
            out[C_OFF + (size_t)(b * NG) * 3 + 0] = qx;
            out[C_OFF + (size_t)(b * NG) * 3 + 1] = qy;
            out[C_OFF + (size_t)(b * NG) * 3 + 2] = qz;
        }
    }

    const int lane = tid & 31, wid = tid >> 5;
    for (int k = 1; k < NG; k++) {
        const unsigned long long nqx2 = pk2(-qx, -qx);
        const unsigned long long nqy2 = pk2(-qy, -qy);
        const unsigned long long nqz2 = pk2(-qz, -qz);
        float v = -1.0f; unsigned vi = 0;
#pragma unroll
        for (int j = 0; j < 8; j++) {
            unsigned long long dx2 = add2(pxx[j], nqx2);
            unsigned long long dy2 = add2(pyy[j], nqy2);
            unsigned long long dz2 = add2(pzz[j], nqz2);
            unsigned long long t  = mul2(dx2, dx2);
            t = fma2(dy2, dy2, t);
            t = fma2(dz2, dz2, t);
            float dlo, dhi; upk2(t, dlo, dhi);
            float nd = fminf(dist[2 * j], dlo);
            dist[2 * j] = nd;
            if (nd > v) { v = nd; vi = (unsigned)((2 * j) * FT + tid); }
            nd = fminf(dist[2 * j + 1], dhi);
            dist[2 * j + 1] = nd;
            if (nd > v) { v = nd; vi = (unsigned)((2 * j + 1) * FT + tid); }
        }
        unsigned vb = __float_as_uint(v);
        unsigned M  = __reduce_max_sync(FULLMASK, vb);
        unsigned cand = (vb == M) ? vi : 0xffffffffu;
        unsigned mi = __reduce_min_sync(FULLMASK, cand);
        const int slot = (k & 1) << 4;
        if (lane == 0) { sv[slot + wid] = M; sidx[slot + wid] = mi; }
        __syncthreads();
        int l = slot + (lane & 15);
        unsigned pv = sv[l], pi = sidx[l];
        unsigned M2 = __reduce_max_sync(FULLMASK, pv);
        unsigned cand2 = (pv == M2) ? pi : 0xffffffffu;
        unsigned far = __reduce_min_sync(FULLMASK, cand2);
        qx = sx[far]; qy = sy[far]; qz = sz[far];
        if (tid == 0) {
            g_center[b * NG + k] = make_float4(qx, qy, qz, sumsq3(qx, qy, qz));
            if (out_size >= C_OFF + C_SZ) {
                out[C_OFF + (size_t)(b * NG + k) * 3 + 0] = qx;
                out[C_OFF + (size_t)(b * NG + k) * 3 + 1] = qy;
                out[C_OFF + (size_t)(b * NG + k) * 3 + 2] = qz;
            }
            if ((k & 7) == 7 || k == NG - 1)
                rel_store(&g_prog[b], k);        // release store (no MEMBAR)
        }
    }
}

// ---------------------------------------------------------------------------
// sort role: EXACT R12 code.
// ---------------------------------------------------------------------------
__device__ void sort_role(int b) {
    const int tid = threadIdx.x;
    const int lane = tid & 31, wid = tid >> 5;

    if (tid == 0) { while (atomicAdd(&g_pts_ready[b], 0) == 0) __nanosleep(1000); }
    __syncthreads();

    const float4* pts = g_pts + b * NPTS;
    float xv[16];
    float lmin = PINF, lmax = -PINF;
#pragma unroll
    for (int j = 0; j < 16; j++) {
        xv[j] = pts[j * FT + tid].x;
        lmin = fminf(lmin, xv[j]); lmax = fmaxf(lmax, xv[j]);
    }
#pragma unroll
    for (int off = 16; off > 0; off >>= 1) {
        lmin = fminf(lmin, __shfl_down_sync(FULLMASK, lmin, off));
        lmax = fmaxf(lmax, __shfl_down_sync(FULLMASK, lmax, off));
    }
    if (lane == 0) { s_red[wid] = lmin; s_red[32 + wid] = lmax; }
    if (tid < NSLAB) s_hist[tid] = 0;
    __syncthreads();
    if (tid < 32) {
        float a = (tid < 16) ? s_red[tid] : PINF;
        float c = (tid < 16) ? s_red[32 + tid] : -PINF;
#pragma unroll
        for (int off = 16; off > 0; off >>= 1) {
            a = fminf(a, __shfl_down_sync(FULLMASK, a, off));
            c = fmaxf(c, __shfl_down_sync(FULLMASK, c, off));
        }
        if (tid == 0) { s_mm[0] = a; s_mm[1] = c; }
    }
    __syncthreads();
    const float xmin = s_mm[0];
    const float scale = 255.0f / fmaxf(s_mm[1] - xmin, 1e-20f);
    int bins[16];
#pragma unroll
    for (int j = 0; j < 16; j++) {
        int bn = (int)((xv[j] - xmin) * scale);
        bins[j] = bn < 0 ? 0 : (bn > 255 ? 255 : bn);
        atomicAdd(&s_hist[bins[j]], 1);
    }
    __syncthreads();
    if (tid < 32) {
        int v[8], s = 0;
#pragma unroll
        for (int r = 0; r < 8; r++) { v[r] = s_hist[tid * 8 + r]; s += v[r]; }
        int inc = s;
#pragma unroll
        for (int off = 1; off < 32; off <<= 1) {
            int n = __shfl_up_sync(FULLMASK, inc, off);
            if (tid >= off) inc += n;
        }
        int run = inc - s;
#pragma unroll
        for (int r = 0; r < 8; r++) { int t = v[r]; s_hist[tid * 8 + r] = run; run += t; }
    }
    __syncthreads();
#pragma unroll
    for (int j = 0; j < 16; j++) {
        int i = j * FT + tid;
        int pos = atomicAdd(&s_hist[bins[j]], 1);
        g_spts[b * NPTS + pos] = pts[i];
        g_sidx[b * NPTS + pos] = i;
    }
    __threadfence();
    __syncthreads();
    if (tid < NSLAB) {
        float mn = PINF, mx = -PINF;
#pragma unroll 8
        for (int r = 0; r < 32; r++) {
            float x = g_spts[b * NPTS + tid * 32 + r].x;
            mn = fminf(mn, x); mx = fmaxf(mx, x);
        }
        g_slab[b * NSLAB + tid] = make_float2(mn, mx);
    }
    __threadfence();
    __syncthreads();
    if (tid == 0) atomicExch(&g_sort_done[b], 1);
}

// ---------------------------------------------------------------------------
// kNN role: EXACT R12 code except the g_prog poll is ld.acquire.gpu instead
// of atomicAdd (no L2 atomic-RMW contention on the published line).
// ---------------------------------------------------------------------------
__device__ __forceinline__ float ref_dist(float4 c, float x, float y, float z, float p2) {
    float dot = __fmul_rn(c.x, x);
    dot = __fmaf_rn(c.y, y, dot);
    dot = __fmaf_rn(c.z, z, dot);
    return __fsub_rn(__fadd_rn(c.w, p2), __fmul_rn(2.0f, dot));
}
__device__ __forceinline__ bool key_less(float ad, int ai, float bd, int bi) {
    return (ad < bd) || (ad == bd && ai < bi);
}
__device__ __forceinline__ void sort32(float& Sd, int& Si, int lane) {
#pragma unroll
    for (int k = 2; k <= 32; k <<= 1) {
        const bool dd = (lane & k) != 0;
#pragma unroll
        for (int j = k >> 1; j > 0; j >>= 1) {
            float od = __shfl_xor_sync(FULLMASK, Sd, j);
            int   oi = __shfl_xor_sync(FULLMASK, Si, j);
            bool lower = key_less(od, oi, Sd, Si);
            bool takeSmaller = (((lane & j) == 0) != dd);
            if (lower == takeSmaller) { Sd = od; Si = oi; }
        }
    }
}
__device__ __forceinline__ void bitonic_cleanup(float& Sd, int& Si, int lane) {
#pragma unroll
    for (int j = 16; j > 0; j >>= 1) {
        float od = __shfl_xor_sync(FULLMASK, Sd, j);
        int   oi = __shfl_xor_sync(FULLMASK, Si, j);
        bool lower = key_less(od, oi, Sd, Si);
        bool takeSmaller = ((lane & j) == 0);
        if (lower == takeSmaller) { Sd = od; Si = oi; }
    }
}

__device__ void knn_role(const float* __restrict__ xyz, float* __restrict__ out,
                         int out_size, int kc) {
    const int tid  = threadIdx.x;
    const int lane = tid & 31;
    const int w    = tid >> 5;            // warp in CTA, 0..15
    const int gib  = w >> 1;              // pair, 0..7
    const int role = w & 1;
    const int b    = kc >> 3;             // 8 CTAs per batch
    const int cib  = kc & 7;
    const unsigned lmlt = (1u << lane) - 1u;

    if (lane == 0) { while (atomicAdd(&g_sort_done[b], 0) == 0) __nanosleep(1000); }
    __syncwarp();
    if (tid < NSLAB) k_slab[tid] = g_slab[b * NSLAB + tid];
    __syncthreads();

    const float4* sp = g_spts + b * NPTS;
    const int*    si = g_sidx + b * NPTS;

    for (int t = 0; t < 8; t++) {
        const int k_id = t * 64 + cib * 8 + gib;
        const int grp  = b * NG + k_id;
        if (lane == 0) { while (acq_load(&g_prog[b]) < k_id) __nanosleep(400); }
        __syncwarp();
        const float4 c = __ldcg(&g_center[grp]);   // L2-fresh (bypass L1)

        int cnt = 0;
#pragma unroll
        for (int r = 0; r < 8; r++) {
            float2 sl = k_slab[r * 32 + lane];
            cnt += __popc(__ballot_sync(FULLMASK, sl.x <= c.x));
        }
        const int s0 = cnt > 0 ? cnt - 1 : 0;

        float Sd = PINF; int Si = 0x7fffffff;
        float Td = PINF; int Ti = 0x7fffffff;
        int bcnt = 0;

        auto merge_buf = [&](int take) {
            float bd = (lane < take) ? k_bufD[w][lane] : PINF;
            int   bi = (lane < take) ? k_bufI[w][lane] : 0x7fffffff;
            sort32(bd, bi, lane);
            float rd = __shfl_sync(FULLMASK, bd, 31 - lane);
            int   ri = __shfl_sync(FULLMASK, bi, 31 - lane);
            if (key_less(rd, ri, Sd, Si)) { Sd = rd; Si = ri; }
            bitonic_cleanup(Sd, Si, lane);
            int rem = bcnt - take;
            if (lane < rem) { k_bufD[w][lane] = k_bufD[w][32 + lane]; k_bufI[w][lane] = k_bufI[w][32 + lane]; }
            bcnt = rem;
            Td = __shfl_sync(FULLMASK, Sd, 31);
            Ti = __shfl_sync(FULLMASK, Si, 31);
        };

        auto process = [&](int s) {
            float2 sl = k_slab[s];
            float lb = fmaxf(fmaxf(sl.x - c.x, c.x - sl.y), 0.0f);
            if (__fmul_rn(__fmul_rn(lb, lb), 0.98f) > Td) return;   // safe-margin skip
            const int base = s * 32;
            float4 p = sp[base + lane];
            int    oi = si[base + lane];
            float d = ref_dist(c, p.x, p.y, p.z, p.w);
            bool qf = key_less(d, oi, Td, Ti);
            unsigned m = __ballot_sync(FULLMASK, qf);
            if (m) {
                int pos = bcnt + __popc(m & lmlt);
                if (qf) { k_bufD[w][pos] = d; k_bufI[w][pos] = oi; }
                bcnt += __popc(m);
                if (bcnt >= 32) merge_buf(32);
            }
        };

        if (role == 0) { for (int s = s0; s < NSLAB; s++) process(s); }
        else           { for (int s = s0 - 1; s >= 0; s--) process(s); }
        if (bcnt > 0) merge_buf(bcnt);

        if (role == 1) { k_mD[gib][lane] = Sd; k_mI[gib][lane] = Si; }
        asm volatile("bar.sync %0, %1;" :: "r"(gib + 1), "r"(64) : "memory");
        if (role == 0) {
            float rd = k_mD[gib][31 - lane];
            int   ri = k_mI[gib][31 - lane];
            if (key_less(rd, ri, Sd, Si)) { Sd = rd; Si = ri; }
            bitonic_cleanup(Sd, Si, lane);

            const int n = Si;
            float4 pw = g_pts[b * NPTS + n];
            const float* pb = xyz + ((size_t)b * NPTS + n) * CDIM;
            float e0 = pb[3], e1 = pb[4], e2 = pb[5];
            float2 w0 = make_float2(pw.x - c.x, pw.y - c.y);
            float2 w1 = make_float2(pw.z - c.z, e0);
            float2 w2 = make_float2(e1, e2);
            float2* ob = (float2*)out + ((size_t)grp * GS + lane) * 3;
            ob[0] = w0; ob[1] = w1; ob[2] = w2;
            if (out_size >= I_OFF + I_SZ)
                out[I_OFF + (size_t)grp * GS + lane] = (float)n;
        }
        asm volatile("bar.sync %0, %1;" :: "r"(gib + 1), "r"(64) : "memory");
    }
}

// ---------------------------------------------------------------------------
__global__ void init_kernel() {
    int i = threadIdx.x;
    if (i < BATCH) { g_prog[i] = -1; g_pts_ready[i] = 0; g_sort_done[i] = 0; }
}

extern __shared__ char dyn_smem[];
__global__ void __launch_bounds__(FT, 1)
fused_kernel(const float* __restrict__ xyz, float* __restrict__ out, int out_size) {
    const int bid = blockIdx.x;
    if (bid < 8)       fps_role(xyz, out, out_size, bid, dyn_smem);
    else if (bid < 16) sort_role(bid - 8);
    else               knn_role(xyz, out, out_size, bid - 16);
}

extern "C" void kernel_launch(void* const* d_in, const int* in_sizes, int n_in,
                              void* d_out, int out_size) {
    const float* xyz = (const float*)d_in[0];
    float* out = (float*)d_out;
    (void)in_sizes; (void)n_in;

    cudaFuncSetAttribute(fused_kernel, cudaFuncAttributeMaxDynamicSharedMemorySize,
                         (int)FPS_SMEM);
    init_kernel<<<1, 32>>>();
    fused_kernel<<<80, FT, FPS_SMEM>>>(xyz, out, out_size);
}